// round 8
// baseline (speedup 1.0000x reference)
#include <cuda_runtime.h>
#include <cuda_fp16.h>
#include <math.h>
#include <stdint.h>

#define BB 2
#define SS 2047
#define NN 2048
#define CC 1024
#define HH 16
#define DD 64

// Scratch (device globals; no runtime allocation allowed)
__device__ __half g_xg_h[BB * NN * CC];     // (B, N, C) input + global token, fp16
__device__ __half g_wqkv_h[3 * CC * CC];    // fp16 weights
__device__ __half g_wproj_h[CC * CC];
__device__ __half g_q_h[BB * NN * CC];      // (B, N, H, D) fp16; q pre-scaled 0.125*log2(e)
__device__ __half g_k_h[BB * NN * CC];
__device__ __half g_v_h[BB * NN * CC];
__device__ __half g_ao_h[BB * NN * CC];     // attention out, fp16 (B, N, H, D)

// ---------------------------------------------------------------------------
// PTX helpers (baseline features only — harness targets plain compute_103)
// ---------------------------------------------------------------------------
__device__ __forceinline__ uint32_t s2u(const void* p) {
    uint32_t a;
    asm("{ .reg .u64 t; cvta.to.shared.u64 t, %1; cvt.u32.u64 %0, t; }" : "=r"(a) : "l"(p));
    return a;
}
__device__ __forceinline__ void cpa16(uint32_t s, const void* g) {
    asm volatile("cp.async.cg.shared.global [%0], [%1], 16;\n" :: "r"(s), "l"(g));
}
__device__ __forceinline__ void cpa_commit() {
    asm volatile("cp.async.commit_group;\n" ::: "memory");
}
template <int N>
__device__ __forceinline__ void cpa_wait() {
    asm volatile("cp.async.wait_group %0;\n" :: "n"(N) : "memory");
}
__device__ __forceinline__ void ldm_x4(uint32_t& r0, uint32_t& r1, uint32_t& r2, uint32_t& r3,
                                       uint32_t addr) {
    asm volatile("ldmatrix.sync.aligned.m8n8.x4.shared.b16 {%0,%1,%2,%3}, [%4];"
                 : "=r"(r0), "=r"(r1), "=r"(r2), "=r"(r3) : "r"(addr));
}
__device__ __forceinline__ void ldm_x4t(uint32_t& r0, uint32_t& r1, uint32_t& r2, uint32_t& r3,
                                        uint32_t addr) {
    asm volatile("ldmatrix.sync.aligned.m8n8.x4.trans.shared.b16 {%0,%1,%2,%3}, [%4];"
                 : "=r"(r0), "=r"(r1), "=r"(r2), "=r"(r3) : "r"(addr));
}
__device__ __forceinline__ void mma_f16(float& d0, float& d1, float& d2, float& d3,
                                        uint32_t a0, uint32_t a1, uint32_t a2, uint32_t a3,
                                        uint32_t b0, uint32_t b1) {
    asm volatile(
        "mma.sync.aligned.m16n8k16.row.col.f32.f16.f16.f32 "
        "{%0,%1,%2,%3}, {%4,%5,%6,%7}, {%8,%9}, {%0,%1,%2,%3};"
        : "+f"(d0), "+f"(d1), "+f"(d2), "+f"(d3)
        : "r"(a0), "r"(a1), "r"(a2), "r"(a3), "r"(b0), "r"(b1));
}
// fp16-accumulated variant (2x rate). C layout matches the fp32 frag positions.
__device__ __forceinline__ void mma_f16acc(uint32_t& d0, uint32_t& d1,
                                           uint32_t a0, uint32_t a1, uint32_t a2, uint32_t a3,
                                           uint32_t b0, uint32_t b1) {
    asm volatile(
        "mma.sync.aligned.m16n8k16.row.col.f16.f16.f16.f16 "
        "{%0,%1}, {%2,%3,%4,%5}, {%6,%7}, {%0,%1};"
        : "+r"(d0), "+r"(d1)
        : "r"(a0), "r"(a1), "r"(a2), "r"(a3), "r"(b0), "r"(b1));
}
__device__ __forceinline__ uint32_t packh2(float a, float b) {
    __half2 h = __floats2half2_rn(a, b);
    return *(uint32_t*)&h;
}
__device__ __forceinline__ float2 unpackh2(uint32_t u) {
    __half2 h = *(__half2*)&u;
    return __half22float2(h);
}

// ---------------------------------------------------------------------------
// Fused prep: fp16-convert both weight matrices + build xg (global||x).
// ---------------------------------------------------------------------------
__global__ void prep_kernel(const float4* __restrict__ x, const float4* __restrict__ gt,
                            const float4* __restrict__ qkv_w, const float4* __restrict__ proj_w) {
    int i = blockIdx.x * blockDim.x + threadIdx.x;
    float4 v;
    uint2* dst;
    if (i < 786432) {
        v = qkv_w[i];
        dst = (uint2*)g_wqkv_h + i;
    } else if (i < 1048576) {
        int j = i - 786432;
        v = proj_w[j];
        dst = (uint2*)g_wproj_h + j;
    } else {
        int j = i - 1048576;
        const int C4 = CC / 4;
        int c4 = j % C4;
        int n  = (j / C4) % NN;
        int b  = j / (C4 * NN);
        if (n == 0) v = gt[c4];
        else        v = x[((size_t)b * SS + (n - 1)) * C4 + c4];
        dst = (uint2*)g_xg_h + j;
    }
    uint2 o;
    o.x = packh2(v.x, v.y);
    o.y = packh2(v.z, v.w);
    *dst = o;
}

// ---------------------------------------------------------------------------
// fp16 mma.sync GEMM, chunked fp16 accumulation:
//   per BK=64 chunk accumulate in fp16 C-frags (2x HMMA rate), drain to fp32
//   once per chunk (bounded rounding: 64 roundings at <=0.18x final magnitude).
// Tile 128x128, 256 threads / 8 warps (2x4), warp tile 64x32.
// MODE 0: QKV -> fp16 q/k/v (B,N,H,D), q scaled 0.125*log2(e).
// MODE 1: proj -> +bias, skip global-token row, fp32 out.
// ---------------------------------------------------------------------------
#define BKH 64
#define ROWB 144
#define TILEB (128 * ROWB)
#define STAGEB (2 * TILEB)
#define NCHUNK (CC / BKH)
#define GEMM_SMEM (2 * STAGEB)
#define QSCALE 0.180336880111f   // 0.125 * log2(e)

__device__ __forceinline__ void ldtile256(const __half* __restrict__ base, int row0,
                                          int kc, uint32_t s, int tid) {
#pragma unroll
    for (int i = 0; i < 4; i++) {
        int idx = i * 256 + tid;
        int row = idx >> 3, seg = idx & 7;
        cpa16(s + row * ROWB + seg * 16,
              base + (size_t)(row0 + row) * CC + kc * BKH + seg * 8);
    }
}

template <int MODE>
__global__ __launch_bounds__(256) void gemm_h_kernel(const __half* __restrict__ A,
                                                     const __half* __restrict__ W,
                                                     const float* __restrict__ bias,
                                                     float* __restrict__ out) {
    extern __shared__ __align__(1024) char dsm[];
    const int tid  = threadIdx.x;
    const int w    = tid >> 5, lane = tid & 31;
    const int wr   = w >> 2, wc = w & 3;          // 2 x 4 warp grid
    const int row0 = blockIdx.y * 128;
    const int col0 = blockIdx.x * 128;

    uint32_t sb = s2u(dsm);

    float d[4][4][4];
#pragma unroll
    for (int mt = 0; mt < 4; mt++)
#pragma unroll
        for (int nt = 0; nt < 4; nt++)
#pragma unroll
            for (int i = 0; i < 4; i++) d[mt][nt][i] = 0.f;

    ldtile256(A, row0, 0, sb, tid);
    ldtile256(W, col0, 0, sb + TILEB, tid);
    cpa_commit();
    ldtile256(A, row0, 1, sb + STAGEB, tid);
    ldtile256(W, col0, 1, sb + STAGEB + TILEB, tid);
    cpa_commit();

    const uint32_t aw_row = (lane & 15);
    const uint32_t aw_k16 = (lane >> 4) * 16;
    const uint32_t bw_row = (lane & 7) + ((lane >> 4) & 1) * 8;
    const uint32_t bw_k16 = ((lane >> 3) & 1) * 16;

    for (int kc = 0; kc < NCHUNK; kc++) {
        cpa_wait<1>();
        __syncthreads();
        uint32_t As = sb + (kc & 1) * STAGEB + (wr * 64) * ROWB;
        uint32_t Bs = sb + (kc & 1) * STAGEB + TILEB + (wc * 32) * ROWB;

        uint32_t dh[4][4][2];
#pragma unroll
        for (int mt = 0; mt < 4; mt++)
#pragma unroll
            for (int nt = 0; nt < 4; nt++) { dh[mt][nt][0] = 0u; dh[mt][nt][1] = 0u; }

#pragma unroll
        for (int ks = 0; ks < 4; ks++) {
            uint32_t kb = ks * 32;
            uint32_t a[4][4];
#pragma unroll
            for (int mt = 0; mt < 4; mt++) {
                uint32_t addr = As + (mt * 16 + aw_row) * ROWB + kb + aw_k16;
                ldm_x4(a[mt][0], a[mt][1], a[mt][2], a[mt][3], addr);
            }
            uint32_t bf[4][2];
#pragma unroll
            for (int np = 0; np < 2; np++) {
                uint32_t addr = Bs + (np * 16 + bw_row) * ROWB + kb + bw_k16;
                uint32_t r0, r1, r2, r3;
                ldm_x4(r0, r1, r2, r3, addr);
                bf[2 * np + 0][0] = r0; bf[2 * np + 0][1] = r1;
                bf[2 * np + 1][0] = r2; bf[2 * np + 1][1] = r3;
            }
#pragma unroll
            for (int mt = 0; mt < 4; mt++)
#pragma unroll
                for (int nt = 0; nt < 4; nt++)
                    mma_f16acc(dh[mt][nt][0], dh[mt][nt][1],
                               a[mt][0], a[mt][1], a[mt][2], a[mt][3],
                               bf[nt][0], bf[nt][1]);
        }

        // Drain fp16 chunk accumulators into fp32
#pragma unroll
        for (int mt = 0; mt < 4; mt++)
#pragma unroll
            for (int nt = 0; nt < 4; nt++) {
                float2 f0 = unpackh2(dh[mt][nt][0]);
                float2 f1 = unpackh2(dh[mt][nt][1]);
                d[mt][nt][0] += f0.x; d[mt][nt][1] += f0.y;
                d[mt][nt][2] += f1.x; d[mt][nt][3] += f1.y;
            }

        __syncthreads();
        if (kc + 2 < NCHUNK) {
            uint32_t s = sb + (kc & 1) * STAGEB;
            ldtile256(A, row0, kc + 2, s, tid);
            ldtile256(W, col0, kc + 2, s + TILEB, tid);
        }
        cpa_commit();
    }

#pragma unroll
    for (int mt = 0; mt < 4; mt++) {
        int mg = row0 + wr * 64 + mt * 16 + (lane >> 2);
#pragma unroll
        for (int nt = 0; nt < 4; nt++) {
            int ng = col0 + wc * 32 + nt * 8 + (lane & 3) * 2;
#pragma unroll
            for (int hi = 0; hi < 2; hi++) {
                int rowg = mg + hi * 8;
                float v0 = d[mt][nt][hi * 2 + 0];
                float v1 = d[mt][nt][hi * 2 + 1];
                if (MODE == 0) {
                    int which = ng >> 10;
                    int p = ng & 1023;
                    float sc = (which == 0) ? QSCALE : 1.0f;
                    __half* dst = ((which == 0) ? g_q_h : (which == 1) ? g_k_h : g_v_h)
                                  + (size_t)rowg * CC + p;
                    *(uint32_t*)dst = packh2(v0 * sc, v1 * sc);
                } else {
                    int b = rowg >> 11, n = rowg & (NN - 1);
                    if (n > 0) {
                        float* dst = out + ((size_t)(b * SS + n - 1)) * CC + ng;
                        dst[0] = v0 + bias[ng];
                        dst[1] = v1 + bias[ng + 1];
                    }
                }
            }
        }
    }
}

// ---------------------------------------------------------------------------
// Tensor-core flash attention (block-causal, no max subtraction).
// CTA = (b, h, 128 queries): 8 warps x 16 rows — per-warp shape identical to
// the 64-query version, but K/V global traffic is halved. Warps 0-3 skip the
// final key tile (block-causal @64); barriers stay uniform.
// S = Q K^T fp16-acc; p = exp2(s); S C-frags reused as PV A-frags; O fp32.
// ---------------------------------------------------------------------------
#define AROWB 144
#define QTILE (128 * AROWB)
#define KVTILE (64 * AROWB)
#define ATTN_SMEM (QTILE + 4 * KVTILE)

__device__ __forceinline__ void ld_kv_tile(uint32_t s, const __half* __restrict__ g, int tid) {
#pragma unroll
    for (int i = 0; i < 2; i++) {
        int idx = i * 256 + tid;
        int row = idx >> 3, seg = idx & 7;
        cpa16(s + row * AROWB + seg * 16, g + (size_t)row * CC + seg * 8);
    }
}

__global__ __launch_bounds__(256) void fattn_kernel() {
    extern __shared__ __align__(1024) char asmem[];
    const int b = blockIdx.z, h = blockIdx.y;
    const int qb2 = (int)(gridDim.x - 1 - blockIdx.x);   // heaviest CTAs first
    const int tid = threadIdx.x, w = tid >> 5, lane = tid & 31;

    uint32_t sb = s2u(asmem);
    uint32_t Qs = sb;
    uint32_t Ks[2] = {sb + QTILE, sb + QTILE + KVTILE};
    uint32_t Vs[2] = {sb + QTILE + 2 * KVTILE, sb + QTILE + 3 * KVTILE};

    const __half* qg = g_q_h + ((size_t)(b * NN + qb2 * 128)) * CC + h * DD;
    const __half* kg = g_k_h + ((size_t)b * NN) * CC + h * DD;
    const __half* vg = g_v_h + ((size_t)b * NN) * CC + h * DD;

#pragma unroll
    for (int i = 0; i < 4; i++) {
        int idx = i * 256 + tid;
        int row = idx >> 3, seg = idx & 7;
        cpa16(Qs + row * AROWB + seg * 16, qg + (size_t)row * CC + seg * 8);
    }
    ld_kv_tile(Ks[0], kg, tid);
    ld_kv_tile(Vs[0], vg, tid);
    cpa_commit();
    cpa_wait<0>();
    __syncthreads();

    const uint32_t aw_row = (lane & 15);
    const uint32_t aw_k16 = (lane >> 4) * 16;
    const uint32_t bw_row = (lane & 7) + ((lane >> 4) & 1) * 8;
    const uint32_t bw_k16 = ((lane >> 3) & 1) * 16;
    uint32_t qf[4][4];
#pragma unroll
    for (int kc = 0; kc < 4; kc++) {
        uint32_t addr = Qs + (w * 16 + aw_row) * AROWB + kc * 32 + aw_k16;
        ldm_x4(qf[kc][0], qf[kc][1], qf[kc][2], qf[kc][3], addr);
    }

    float o[8][4];
#pragma unroll
    for (int nt = 0; nt < 8; nt++)
#pragma unroll
        for (int i = 0; i < 4; i++) o[nt][i] = 0.f;
    float l0 = 0.f, l1 = 0.f;

    const int ntiles = 2 * qb2 + 2;
    const int limit  = 2 * qb2 + 1 + (w >> 2);   // warps 4-7 see one more tile

    for (int j = 0; j < ntiles; j++) {
        if (j + 1 < ntiles) {
            ld_kv_tile(Ks[(j + 1) & 1], kg + (size_t)((j + 1) * 64) * CC, tid);
            ld_kv_tile(Vs[(j + 1) & 1], vg + (size_t)((j + 1) * 64) * CC, tid);
            cpa_commit();
            cpa_wait<1>();
        } else {
            cpa_wait<0>();
        }
        __syncthreads();

        if (j < limit) {
            uint32_t K = Ks[j & 1], V = Vs[j & 1];

            uint32_t sh[8][2];
#pragma unroll
            for (int nt = 0; nt < 8; nt++) { sh[nt][0] = 0u; sh[nt][1] = 0u; }
#pragma unroll
            for (int ks = 0; ks < 4; ks++) {
                uint32_t kb = ks * 32;
                uint32_t bf[8][2];
#pragma unroll
                for (int np = 0; np < 4; np++) {
                    uint32_t addr = K + (np * 16 + bw_row) * AROWB + kb + bw_k16;
                    uint32_t r0, r1, r2, r3;
                    ldm_x4(r0, r1, r2, r3, addr);
                    bf[2 * np + 0][0] = r0; bf[2 * np + 0][1] = r1;
                    bf[2 * np + 1][0] = r2; bf[2 * np + 1][1] = r3;
                }
#pragma unroll
                for (int nt = 0; nt < 8; nt++)
                    mma_f16acc(sh[nt][0], sh[nt][1],
                               qf[ks][0], qf[ks][1], qf[ks][2], qf[ks][3],
                               bf[nt][0], bf[nt][1]);
            }

#pragma unroll
            for (int nt = 0; nt < 8; nt++) {
                float2 f0 = unpackh2(sh[nt][0]);
                float2 f1 = unpackh2(sh[nt][1]);
                float p0 = exp2f(f0.x), p1 = exp2f(f0.y);
                float p2 = exp2f(f1.x), p3 = exp2f(f1.y);
                l0 += p0 + p1;
                l1 += p2 + p3;
                sh[nt][0] = packh2(p0, p1);
                sh[nt][1] = packh2(p2, p3);
            }

#pragma unroll
            for (int kc = 0; kc < 4; kc++) {
#pragma unroll
                for (int dp = 0; dp < 4; dp++) {
                    uint32_t addr = V + (kc * 16 + (lane & 7) + ((lane >> 3) & 1) * 8) * AROWB
                                  + (dp * 16 + (lane >> 4) * 8) * 2;
                    uint32_t r0, r1, r2, r3;
                    ldm_x4t(r0, r1, r2, r3, addr);
                    mma_f16(o[2 * dp][0], o[2 * dp][1], o[2 * dp][2], o[2 * dp][3],
                            sh[2 * kc][0], sh[2 * kc][1], sh[2 * kc + 1][0], sh[2 * kc + 1][1],
                            r0, r1);
                    mma_f16(o[2 * dp + 1][0], o[2 * dp + 1][1], o[2 * dp + 1][2], o[2 * dp + 1][3],
                            sh[2 * kc][0], sh[2 * kc][1], sh[2 * kc + 1][0], sh[2 * kc + 1][1],
                            r2, r3);
                }
            }
        }
        __syncthreads();
    }

    l0 += __shfl_xor_sync(0xffffffffu, l0, 1);
    l0 += __shfl_xor_sync(0xffffffffu, l0, 2);
    l1 += __shfl_xor_sync(0xffffffffu, l1, 1);
    l1 += __shfl_xor_sync(0xffffffffu, l1, 2);
    float inv0 = 1.f / l0, inv1 = 1.f / l1;

    int row0 = qb2 * 128 + w * 16 + (lane >> 2);
    __half* ao = g_ao_h + ((size_t)b * NN) * CC + h * DD;
#pragma unroll
    for (int nt = 0; nt < 8; nt++) {
        int col = nt * 8 + (lane & 3) * 2;
        *(uint32_t*)(ao + (size_t)row0 * CC + col)       = packh2(o[nt][0] * inv0, o[nt][1] * inv0);
        *(uint32_t*)(ao + (size_t)(row0 + 8) * CC + col) = packh2(o[nt][2] * inv1, o[nt][3] * inv1);
    }
}

// ---------------------------------------------------------------------------
extern "C" void kernel_launch(void* const* d_in, const int* in_sizes, int n_in,
                              void* d_out, int out_size) {
    const float* x      = (const float*)d_in[0];
    const float* gt     = (const float*)d_in[1];
    const float* qkv_w  = (const float*)d_in[2];
    const float* proj_w = (const float*)d_in[3];
    const float* proj_b = (const float*)d_in[4];
    float* out = (float*)d_out;

    cudaFuncSetAttribute(gemm_h_kernel<0>, cudaFuncAttributeMaxDynamicSharedMemorySize, GEMM_SMEM);
    cudaFuncSetAttribute(gemm_h_kernel<1>, cudaFuncAttributeMaxDynamicSharedMemorySize, GEMM_SMEM);
    cudaFuncSetAttribute(fattn_kernel, cudaFuncAttributeMaxDynamicSharedMemorySize, ATTN_SMEM);

    __half *wqkv_h, *wproj_h, *xg_h, *ao_h;
    cudaGetSymbolAddress((void**)&wqkv_h, g_wqkv_h);
    cudaGetSymbolAddress((void**)&wproj_h, g_wproj_h);
    cudaGetSymbolAddress((void**)&xg_h, g_xg_h);
    cudaGetSymbolAddress((void**)&ao_h, g_ao_h);

    prep_kernel<<<8192, 256>>>((const float4*)x, (const float4*)gt,
                               (const float4*)qkv_w, (const float4*)proj_w);

    // QKV GEMM: 4096 x 3072 x 1024 -> fp16 q/k/v (chunked fp16 accumulation)
    gemm_h_kernel<0><<<dim3(24, 32), 256, GEMM_SMEM>>>(xg_h, wqkv_h, nullptr, nullptr);

    // Tensor-core flash attention (128 queries / CTA, 8 warps)
    fattn_kernel<<<dim3(NN / 128, HH, BB), 256, ATTN_SMEM>>>();

    // Output projection: 4096 x 1024 x 1024 (+bias, row skip)
    gemm_h_kernel<1><<<dim3(8, 32), 256, GEMM_SMEM>>>(ao_h, wproj_h, proj_b, out);
}

// round 9
// speedup vs baseline: 1.1754x; 1.1754x over previous
#include <cuda_runtime.h>
#include <cuda_fp16.h>
#include <math.h>
#include <stdint.h>

#define BB 2
#define SS 2047
#define NN 2048
#define CC 1024
#define HH 16
#define DD 64

// Scratch (device globals; no runtime allocation allowed)
__device__ __half g_xg_h[BB * NN * CC];     // (B, N, C) input + global token, fp16
__device__ __half g_wqkv_h[3 * CC * CC];    // fp16 weights
__device__ __half g_wproj_h[CC * CC];
__device__ __half g_q_h[BB * NN * CC];      // (B, N, H, D) fp16; q pre-scaled 0.125*log2(e)
__device__ __half g_k_h[BB * NN * CC];
__device__ __half g_v_h[BB * NN * CC];
__device__ __half g_ao_h[BB * NN * CC];     // attention out, fp16 (B, N, H, D)

// ---------------------------------------------------------------------------
// PTX helpers (baseline features only — harness targets plain compute_103)
// ---------------------------------------------------------------------------
__device__ __forceinline__ uint32_t s2u(const void* p) {
    uint32_t a;
    asm("{ .reg .u64 t; cvta.to.shared.u64 t, %1; cvt.u32.u64 %0, t; }" : "=r"(a) : "l"(p));
    return a;
}
__device__ __forceinline__ void cpa16(uint32_t s, const void* g) {
    asm volatile("cp.async.cg.shared.global [%0], [%1], 16;\n" :: "r"(s), "l"(g));
}
__device__ __forceinline__ void cpa_commit() {
    asm volatile("cp.async.commit_group;\n" ::: "memory");
}
template <int N>
__device__ __forceinline__ void cpa_wait() {
    asm volatile("cp.async.wait_group %0;\n" :: "n"(N) : "memory");
}
__device__ __forceinline__ void ldm_x4(uint32_t& r0, uint32_t& r1, uint32_t& r2, uint32_t& r3,
                                       uint32_t addr) {
    asm volatile("ldmatrix.sync.aligned.m8n8.x4.shared.b16 {%0,%1,%2,%3}, [%4];"
                 : "=r"(r0), "=r"(r1), "=r"(r2), "=r"(r3) : "r"(addr));
}
__device__ __forceinline__ void ldm_x4t(uint32_t& r0, uint32_t& r1, uint32_t& r2, uint32_t& r3,
                                        uint32_t addr) {
    asm volatile("ldmatrix.sync.aligned.m8n8.x4.trans.shared.b16 {%0,%1,%2,%3}, [%4];"
                 : "=r"(r0), "=r"(r1), "=r"(r2), "=r"(r3) : "r"(addr));
}
__device__ __forceinline__ void mma_f16(float& d0, float& d1, float& d2, float& d3,
                                        uint32_t a0, uint32_t a1, uint32_t a2, uint32_t a3,
                                        uint32_t b0, uint32_t b1) {
    asm volatile(
        "mma.sync.aligned.m16n8k16.row.col.f32.f16.f16.f32 "
        "{%0,%1,%2,%3}, {%4,%5,%6,%7}, {%8,%9}, {%0,%1,%2,%3};"
        : "+f"(d0), "+f"(d1), "+f"(d2), "+f"(d3)
        : "r"(a0), "r"(a1), "r"(a2), "r"(a3), "r"(b0), "r"(b1));
}
// fp16-accumulated variant (2x rate).
__device__ __forceinline__ void mma_f16acc(uint32_t& d0, uint32_t& d1,
                                           uint32_t a0, uint32_t a1, uint32_t a2, uint32_t a3,
                                           uint32_t b0, uint32_t b1) {
    asm volatile(
        "mma.sync.aligned.m16n8k16.row.col.f16.f16.f16.f16 "
        "{%0,%1}, {%2,%3,%4,%5}, {%6,%7}, {%0,%1};"
        : "+r"(d0), "+r"(d1)
        : "r"(a0), "r"(a1), "r"(a2), "r"(a3), "r"(b0), "r"(b1));
}
__device__ __forceinline__ uint32_t ex2h2(uint32_t s) {
    uint32_t d;
    asm("ex2.approx.f16x2 %0, %1;" : "=r"(d) : "r"(s));
    return d;
}
__device__ __forceinline__ uint32_t packh2(float a, float b) {
    __half2 h = __floats2half2_rn(a, b);
    return *(uint32_t*)&h;
}

// ---------------------------------------------------------------------------
// Fused prep: fp16-convert both weight matrices + build xg (global||x).
// ---------------------------------------------------------------------------
__global__ void prep_kernel(const float4* __restrict__ x, const float4* __restrict__ gt,
                            const float4* __restrict__ qkv_w, const float4* __restrict__ proj_w) {
    int i = blockIdx.x * blockDim.x + threadIdx.x;
    float4 v;
    uint2* dst;
    if (i < 786432) {
        v = qkv_w[i];
        dst = (uint2*)g_wqkv_h + i;
    } else if (i < 1048576) {
        int j = i - 786432;
        v = proj_w[j];
        dst = (uint2*)g_wproj_h + j;
    } else {
        int j = i - 1048576;
        const int C4 = CC / 4;
        int c4 = j % C4;
        int n  = (j / C4) % NN;
        int b  = j / (C4 * NN);
        if (n == 0) v = gt[c4];
        else        v = x[((size_t)b * SS + (n - 1)) * C4 + c4];
        dst = (uint2*)g_xg_h + j;
    }
    uint2 o;
    o.x = packh2(v.x, v.y);
    o.y = packh2(v.z, v.w);
    *dst = o;
}

// ---------------------------------------------------------------------------
// fp16 mma.sync GEMM (fp32 accum, at the legacy-HMMA f32-acc ceiling):
// Tile 128x128, BK=64 halves, 128 threads / 4 warps (2x2), warp tile 64x64.
// MODE 0: QKV -> fp16 q/k/v (B,N,H,D), q scaled 0.125*log2(e).
// MODE 1: proj -> +bias, skip global-token row, fp32 out.
// ---------------------------------------------------------------------------
#define BKH 64
#define ROWB 144
#define TILEB (128 * ROWB)
#define STAGEB (2 * TILEB)
#define NCHUNK (CC / BKH)
#define GEMM_SMEM (2 * STAGEB)
#define QSCALE 0.180336880111f   // 0.125 * log2(e)

__device__ __forceinline__ void ldtile128(const __half* __restrict__ base, int row0,
                                          int kc, uint32_t s, int tid) {
#pragma unroll
    for (int i = 0; i < 8; i++) {
        int idx = i * 128 + tid;
        int row = idx >> 3, seg = idx & 7;
        cpa16(s + row * ROWB + seg * 16,
              base + (size_t)(row0 + row) * CC + kc * BKH + seg * 8);
    }
}

template <int MODE>
__global__ __launch_bounds__(128) void gemm_h_kernel(const __half* __restrict__ A,
                                                     const __half* __restrict__ W,
                                                     const float* __restrict__ bias,
                                                     float* __restrict__ out) {
    extern __shared__ __align__(1024) char dsm[];
    const int tid  = threadIdx.x;
    const int w    = tid >> 5, lane = tid & 31;
    const int wr   = w >> 1, wc = w & 1;
    const int row0 = blockIdx.y * 128;
    const int col0 = blockIdx.x * 128;

    uint32_t sb = s2u(dsm);

    float d[4][8][4];
#pragma unroll
    for (int mt = 0; mt < 4; mt++)
#pragma unroll
        for (int nt = 0; nt < 8; nt++)
#pragma unroll
            for (int i = 0; i < 4; i++) d[mt][nt][i] = 0.f;

    ldtile128(A, row0, 0, sb, tid);
    ldtile128(W, col0, 0, sb + TILEB, tid);
    cpa_commit();
    ldtile128(A, row0, 1, sb + STAGEB, tid);
    ldtile128(W, col0, 1, sb + STAGEB + TILEB, tid);
    cpa_commit();

    const uint32_t aw_row = (lane & 15);
    const uint32_t aw_k16 = (lane >> 4) * 16;
    const uint32_t bw_row = (lane & 7) + ((lane >> 4) & 1) * 8;
    const uint32_t bw_k16 = ((lane >> 3) & 1) * 16;

    for (int kc = 0; kc < NCHUNK; kc++) {
        cpa_wait<1>();
        __syncthreads();
        uint32_t As = sb + (kc & 1) * STAGEB + (wr * 64) * ROWB;
        uint32_t Bs = sb + (kc & 1) * STAGEB + TILEB + (wc * 64) * ROWB;
#pragma unroll
        for (int ks = 0; ks < 4; ks++) {
            uint32_t kb = ks * 32;
            uint32_t a[4][4];
#pragma unroll
            for (int mt = 0; mt < 4; mt++) {
                uint32_t addr = As + (mt * 16 + aw_row) * ROWB + kb + aw_k16;
                ldm_x4(a[mt][0], a[mt][1], a[mt][2], a[mt][3], addr);
            }
            uint32_t bf[8][2];
#pragma unroll
            for (int np = 0; np < 4; np++) {
                uint32_t addr = Bs + (np * 16 + bw_row) * ROWB + kb + bw_k16;
                uint32_t r0, r1, r2, r3;
                ldm_x4(r0, r1, r2, r3, addr);
                bf[2 * np + 0][0] = r0; bf[2 * np + 0][1] = r1;
                bf[2 * np + 1][0] = r2; bf[2 * np + 1][1] = r3;
            }
#pragma unroll
            for (int mt = 0; mt < 4; mt++)
#pragma unroll
                for (int nt = 0; nt < 8; nt++)
                    mma_f16(d[mt][nt][0], d[mt][nt][1], d[mt][nt][2], d[mt][nt][3],
                            a[mt][0], a[mt][1], a[mt][2], a[mt][3],
                            bf[nt][0], bf[nt][1]);
        }
        __syncthreads();
        if (kc + 2 < NCHUNK) {
            uint32_t s = sb + (kc & 1) * STAGEB;
            ldtile128(A, row0, kc + 2, s, tid);
            ldtile128(W, col0, kc + 2, s + TILEB, tid);
        }
        cpa_commit();
    }

#pragma unroll
    for (int mt = 0; mt < 4; mt++) {
        int mg = row0 + wr * 64 + mt * 16 + (lane >> 2);
#pragma unroll
        for (int nt = 0; nt < 8; nt++) {
            int ng = col0 + wc * 64 + nt * 8 + (lane & 3) * 2;
#pragma unroll
            for (int hi = 0; hi < 2; hi++) {
                int rowg = mg + hi * 8;
                float v0 = d[mt][nt][hi * 2 + 0];
                float v1 = d[mt][nt][hi * 2 + 1];
                if (MODE == 0) {
                    int which = ng >> 10;
                    int p = ng & 1023;
                    float sc = (which == 0) ? QSCALE : 1.0f;
                    __half* dst = ((which == 0) ? g_q_h : (which == 1) ? g_k_h : g_v_h)
                                  + (size_t)rowg * CC + p;
                    *(uint32_t*)dst = packh2(v0 * sc, v1 * sc);
                } else {
                    int b = rowg >> 11, n = rowg & (NN - 1);
                    if (n > 0) {
                        float* dst = out + ((size_t)(b * SS + n - 1)) * CC + ng;
                        dst[0] = v0 + bias[ng];
                        dst[1] = v1 + bias[ng + 1];
                    }
                }
            }
        }
    }
}

// ---------------------------------------------------------------------------
// Tensor-core flash attention (block-causal, no max subtraction).
// CTA = (b, h, 128 queries): 8 warps x 16 rows (halves K/V global traffic vs
// 64q CTAs). Warps 0-3 skip the final key tile; barriers stay uniform.
// S = Q K^T fp16-acc; p = ex2.approx.f16x2 in place; l via ones-MMA (exact
// fp32, no shuffles); O accumulated fp32 (P V).
// ---------------------------------------------------------------------------
#define AROWB 144
#define QTILE (128 * AROWB)
#define KVTILE (64 * AROWB)
#define ATTN_SMEM (QTILE + 4 * KVTILE)
#define ONESH2 0x3C003C00u   // half2(1.0, 1.0)

__device__ __forceinline__ void ld_kv_tile(uint32_t s, const __half* __restrict__ g, int tid) {
#pragma unroll
    for (int i = 0; i < 2; i++) {
        int idx = i * 256 + tid;
        int row = idx >> 3, seg = idx & 7;
        cpa16(s + row * AROWB + seg * 16, g + (size_t)row * CC + seg * 8);
    }
}

__global__ __launch_bounds__(256) void fattn_kernel() {
    extern __shared__ __align__(1024) char asmem[];
    const int b = blockIdx.z, h = blockIdx.y;
    const int qb2 = (int)(gridDim.x - 1 - blockIdx.x);   // heaviest CTAs first
    const int tid = threadIdx.x, w = tid >> 5, lane = tid & 31;

    uint32_t sb = s2u(asmem);
    uint32_t Qs = sb;
    uint32_t Ks[2] = {sb + QTILE, sb + QTILE + KVTILE};
    uint32_t Vs[2] = {sb + QTILE + 2 * KVTILE, sb + QTILE + 3 * KVTILE};

    const __half* qg = g_q_h + ((size_t)(b * NN + qb2 * 128)) * CC + h * DD;
    const __half* kg = g_k_h + ((size_t)b * NN) * CC + h * DD;
    const __half* vg = g_v_h + ((size_t)b * NN) * CC + h * DD;

#pragma unroll
    for (int i = 0; i < 4; i++) {
        int idx = i * 256 + tid;
        int row = idx >> 3, seg = idx & 7;
        cpa16(Qs + row * AROWB + seg * 16, qg + (size_t)row * CC + seg * 8);
    }
    ld_kv_tile(Ks[0], kg, tid);
    ld_kv_tile(Vs[0], vg, tid);
    cpa_commit();
    cpa_wait<0>();
    __syncthreads();

    const uint32_t aw_row = (lane & 15);
    const uint32_t aw_k16 = (lane >> 4) * 16;
    const uint32_t bw_row = (lane & 7) + ((lane >> 4) & 1) * 8;
    const uint32_t bw_k16 = ((lane >> 3) & 1) * 16;
    uint32_t qf[4][4];
#pragma unroll
    for (int kc = 0; kc < 4; kc++) {
        uint32_t addr = Qs + (w * 16 + aw_row) * AROWB + kc * 32 + aw_k16;
        ldm_x4(qf[kc][0], qf[kc][1], qf[kc][2], qf[kc][3], addr);
    }

    float o[8][4];
#pragma unroll
    for (int nt = 0; nt < 8; nt++)
#pragma unroll
        for (int i = 0; i < 4; i++) o[nt][i] = 0.f;
    float ld0 = 0.f, ld1 = 0.f, ld2 = 0.f, ld3 = 0.f;   // l accumulator (ones-MMA)

    const int ntiles = 2 * qb2 + 2;
    const int limit  = 2 * qb2 + 1 + (w >> 2);   // warps 4-7 see one more tile

    for (int j = 0; j < ntiles; j++) {
        if (j + 1 < ntiles) {
            ld_kv_tile(Ks[(j + 1) & 1], kg + (size_t)((j + 1) * 64) * CC, tid);
            ld_kv_tile(Vs[(j + 1) & 1], vg + (size_t)((j + 1) * 64) * CC, tid);
            cpa_commit();
            cpa_wait<1>();
        } else {
            cpa_wait<0>();
        }
        __syncthreads();

        if (j < limit) {
            uint32_t K = Ks[j & 1], V = Vs[j & 1];

            // S = Q K^T, fp16 accumulation
            uint32_t sh[8][2];
#pragma unroll
            for (int nt = 0; nt < 8; nt++) { sh[nt][0] = 0u; sh[nt][1] = 0u; }
#pragma unroll
            for (int ks = 0; ks < 4; ks++) {
                uint32_t kb = ks * 32;
                uint32_t bf[8][2];
#pragma unroll
                for (int np = 0; np < 4; np++) {
                    uint32_t addr = K + (np * 16 + bw_row) * AROWB + kb + bw_k16;
                    uint32_t r0, r1, r2, r3;
                    ldm_x4(r0, r1, r2, r3, addr);
                    bf[2 * np + 0][0] = r0; bf[2 * np + 0][1] = r1;
                    bf[2 * np + 1][0] = r2; bf[2 * np + 1][1] = r3;
                }
#pragma unroll
                for (int nt = 0; nt < 8; nt++)
                    mma_f16acc(sh[nt][0], sh[nt][1],
                               qf[ks][0], qf[ks][1], qf[ks][2], qf[ks][3],
                               bf[nt][0], bf[nt][1]);
            }

            // p = 2^s in-place on half2 (MUFU.EX2.F16x2); no unpack/pack
#pragma unroll
            for (int nt = 0; nt < 8; nt++) {
                sh[nt][0] = ex2h2(sh[nt][0]);
                sh[nt][1] = ex2h2(sh[nt][1]);
            }

            // l += P . ones  (exact fp32 tensor accumulation; every thread
            // ends up with its full row sum in ld0 / ld2)
#pragma unroll
            for (int kc = 0; kc < 4; kc++)
                mma_f16(ld0, ld1, ld2, ld3,
                        sh[2 * kc][0], sh[2 * kc][1], sh[2 * kc + 1][0], sh[2 * kc + 1][1],
                        ONESH2, ONESH2);

            // O += P V
#pragma unroll
            for (int kc = 0; kc < 4; kc++) {
#pragma unroll
                for (int dp = 0; dp < 4; dp++) {
                    uint32_t addr = V + (kc * 16 + (lane & 7) + ((lane >> 3) & 1) * 8) * AROWB
                                  + (dp * 16 + (lane >> 4) * 8) * 2;
                    uint32_t r0, r1, r2, r3;
                    ldm_x4t(r0, r1, r2, r3, addr);
                    mma_f16(o[2 * dp][0], o[2 * dp][1], o[2 * dp][2], o[2 * dp][3],
                            sh[2 * kc][0], sh[2 * kc][1], sh[2 * kc + 1][0], sh[2 * kc + 1][1],
                            r0, r1);
                    mma_f16(o[2 * dp + 1][0], o[2 * dp + 1][1], o[2 * dp + 1][2], o[2 * dp + 1][3],
                            sh[2 * kc][0], sh[2 * kc][1], sh[2 * kc + 1][0], sh[2 * kc + 1][1],
                            r2, r3);
                }
            }
        }
        __syncthreads();
    }

    float inv0 = 1.f / ld0, inv1 = 1.f / ld2;

    int row0 = qb2 * 128 + w * 16 + (lane >> 2);
    __half* ao = g_ao_h + ((size_t)b * NN) * CC + h * DD;
#pragma unroll
    for (int nt = 0; nt < 8; nt++) {
        int col = nt * 8 + (lane & 3) * 2;
        *(uint32_t*)(ao + (size_t)row0 * CC + col)       = packh2(o[nt][0] * inv0, o[nt][1] * inv0);
        *(uint32_t*)(ao + (size_t)(row0 + 8) * CC + col) = packh2(o[nt][2] * inv1, o[nt][3] * inv1);
    }
}

// ---------------------------------------------------------------------------
extern "C" void kernel_launch(void* const* d_in, const int* in_sizes, int n_in,
                              void* d_out, int out_size) {
    const float* x      = (const float*)d_in[0];
    const float* gt     = (const float*)d_in[1];
    const float* qkv_w  = (const float*)d_in[2];
    const float* proj_w = (const float*)d_in[3];
    const float* proj_b = (const float*)d_in[4];
    float* out = (float*)d_out;

    cudaFuncSetAttribute(gemm_h_kernel<0>, cudaFuncAttributeMaxDynamicSharedMemorySize, GEMM_SMEM);
    cudaFuncSetAttribute(gemm_h_kernel<1>, cudaFuncAttributeMaxDynamicSharedMemorySize, GEMM_SMEM);
    cudaFuncSetAttribute(fattn_kernel, cudaFuncAttributeMaxDynamicSharedMemorySize, ATTN_SMEM);

    __half *wqkv_h, *wproj_h, *xg_h, *ao_h;
    cudaGetSymbolAddress((void**)&wqkv_h, g_wqkv_h);
    cudaGetSymbolAddress((void**)&wproj_h, g_wproj_h);
    cudaGetSymbolAddress((void**)&xg_h, g_xg_h);
    cudaGetSymbolAddress((void**)&ao_h, g_ao_h);

    prep_kernel<<<8192, 256>>>((const float4*)x, (const float4*)gt,
                               (const float4*)qkv_w, (const float4*)proj_w);

    // QKV GEMM: 4096 x 3072 x 1024 -> fp16 q/k/v (f32-acc, at HMMA ceiling)
    gemm_h_kernel<0><<<dim3(24, 32), 128, GEMM_SMEM>>>(xg_h, wqkv_h, nullptr, nullptr);

    // Tensor-core flash attention (128 queries / CTA, 8 warps)
    fattn_kernel<<<dim3(NN / 128, HH, BB), 256, ATTN_SMEM>>>();

    // Output projection: 4096 x 1024 x 1024 (+bias, row skip)
    gemm_h_kernel<1><<<dim3(8, 32), 128, GEMM_SMEM>>>(ao_h, wproj_h, proj_b, out);
}